// round 15
// baseline (speedup 1.0000x reference)
#include <cuda_runtime.h>
#include <cuda_bf16.h>

#define BATCH 4
#define CDIM 128
#define FDIM 128
#define TDIM 512
#define HDIM 256
#define MDIM (FDIM*TDIM)   /* 65536 positions per batch */
#define EPSV 1e-6f

__device__ __forceinline__ float silu_f(float v) {
    return __fdividef(v, 1.f + __expf(-v));
}
__device__ __forceinline__ float glu_f(float a, float g) {
    return __fdividef(a, 1.f + __expf(-g));
}

// ---------------- scratch (static device globals; no runtime alloc) ----------
__device__ __nv_bfloat16 g_Y[(size_t)BATCH * MDIM * CDIM];   //  64 MB  [b][m][c]
__device__ __nv_bfloat16 g_U[(size_t)BATCH * MDIM * HDIM];   // 128 MB  [b][m][h]
__device__ __nv_bfloat16 g_W1[2 * HDIM * CDIM];              // w_in * g_norm (bf16)
__device__ __nv_bfloat16 g_W2[CDIM * HDIM];                  // w_out (bf16)

// ---------------- kernel 0: weight prep --------------------------------------
__global__ void k_prep(const float* __restrict__ w_in,
                       const float* __restrict__ gn,
                       const float* __restrict__ w_out) {
    int i = blockIdx.x * 256 + threadIdx.x;
    if (i < 2 * HDIM * CDIM)
        g_W1[i] = __float2bfloat16(w_in[i] * gn[i & (CDIM - 1)]);
    if (i < CDIM * HDIM)
        g_W2[i] = __float2bfloat16(w_out[i]);
}

// ---------------- kernel 1: RMSNorm + transpose to [m][c] bf16 ---------------
__global__ __launch_bounds__(256) void k_rms(const float* __restrict__ x,
                                             const float* __restrict__ gn) {
    __shared__ float xs[CDIM][65];   // [c][t] padded
    __shared__ float ps[4][64];
    __shared__ float ssc[64];
    __shared__ float gs[CDIM];
    int b = blockIdx.z, f = blockIdx.y, t0 = blockIdx.x * 64;
    int tid = threadIdx.x;
    const float* xb = x + ((size_t)(b * CDIM) * FDIM + f) * TDIM + t0;
    for (int i = tid; i < CDIM * 16; i += 256) {
        int c = i >> 4, q = i & 15;
        float4 v = *(const float4*)(xb + (size_t)c * FDIM * TDIM + q * 4);
        xs[c][q * 4 + 0] = v.x;
        xs[c][q * 4 + 1] = v.y;
        xs[c][q * 4 + 2] = v.z;
        xs[c][q * 4 + 3] = v.w;
    }
    if (tid < CDIM) gs[tid] = gn[tid];
    __syncthreads();
    {
        int t = tid & 63, cs = (tid >> 6) * 32;
        float s = 0.f;
#pragma unroll
        for (int c = 0; c < 32; c++) { float v = xs[cs + c][t]; s += v * v; }
        ps[tid >> 6][t] = s;
    }
    __syncthreads();
    if (tid < 64) {
        float s = ps[0][tid] + ps[1][tid] + ps[2][tid] + ps[3][tid];
        ssc[tid] = rsqrtf(s * (1.0f / CDIM) + EPSV);
    }
    __syncthreads();
    __nv_bfloat16* yb = g_Y + ((size_t)b * MDIM + (size_t)f * TDIM + t0) * CDIM;
    for (int i = tid; i < 64 * 64; i += 256) {
        int t = i >> 6, cp = i & 63;
        float sc = ssc[t];
        float v0 = xs[2 * cp][t] * sc * gs[2 * cp];
        float v1 = xs[2 * cp + 1][t] * sc * gs[2 * cp + 1];
        *(__nv_bfloat162*)(yb + (size_t)t * CDIM + 2 * cp) =
            __floats2bfloat162_rn(v0, v1);
    }
}

// ---------------- mma / ldmatrix / cp.async helpers ---------------------------
__device__ __forceinline__ void mma16816(float* d, const unsigned* a, const unsigned* bb) {
    asm volatile(
        "mma.sync.aligned.m16n8k16.row.col.f32.bf16.bf16.f32 "
        "{%0,%1,%2,%3},{%4,%5,%6,%7},{%8,%9},{%0,%1,%2,%3};\n"
        : "+f"(d[0]), "+f"(d[1]), "+f"(d[2]), "+f"(d[3])
        : "r"(a[0]), "r"(a[1]), "r"(a[2]), "r"(a[3]), "r"(bb[0]), "r"(bb[1]));
}
__device__ __forceinline__ unsigned sptr(const void* p) {
    unsigned r;
    asm("{.reg .u64 t; cvta.to.shared.u64 t, %1; cvt.u32.u64 %0, t;}" : "=r"(r) : "l"(p));
    return r;
}
__device__ __forceinline__ void ldsm4(unsigned addr, unsigned* r) {
    asm volatile("ldmatrix.sync.aligned.m8n8.x4.shared.b16 {%0,%1,%2,%3},[%4];"
                 : "=r"(r[0]), "=r"(r[1]), "=r"(r[2]), "=r"(r[3]) : "r"(addr));
}
__device__ __forceinline__ void cpasync16(unsigned dst, const void* src) {
    asm volatile("cp.async.cg.shared.global [%0], [%1], 16;" :: "r"(dst), "l"(src));
}
__device__ __forceinline__ void cpasync16z(unsigned dst, const void* src, int srcsz) {
    asm volatile("cp.async.cg.shared.global [%0], [%1], 16, %2;"
                 :: "r"(dst), "l"(src), "r"(srcsz));
}
__device__ __forceinline__ void cpcommit() {
    asm volatile("cp.async.commit_group;");
}

// ---------------- kernel 2: GEMM1 pipelined (cp.async, W1-half resident) -----
#define S1 136   // smem row stride (elems)
#define G1SUB 8
__device__ __forceinline__ void g1_stageY(const __nv_bfloat16* src,
                                          __nv_bfloat16* dst, int tid) {
#pragma unroll
    for (int i = tid; i < 32 * 16; i += 256) {
        int m = i >> 4, q = i & 15;
        cpasync16(sptr(dst + m * S1) + (unsigned)(q * 16),
                  src + (size_t)m * CDIM + q * 8);
    }
}
__global__ __launch_bounds__(256, 2) void k_gemm1(const float* __restrict__ b_in) {
    extern __shared__ __nv_bfloat16 sm1[];
    __nv_bfloat16* Was = sm1;                  // [128][S1]
    __nv_bfloat16* Wbs = sm1 + 128 * S1;       // [128][S1]
    __nv_bfloat16* Ybuf[2];
    Ybuf[0] = sm1 + 256 * S1;                  // [32][S1]
    Ybuf[1] = Ybuf[0] + 32 * S1;               // [32][S1]
    int b = blockIdx.z;
    int h0 = blockIdx.y * 128;
    size_t mbase = (size_t)blockIdx.x * 256;
    int tid = threadIdx.x;

#pragma unroll
    for (int i = tid; i < 128 * 16; i += 256) {
        int hh = i >> 4, q = i & 15;
        cpasync16(sptr(Was + hh * S1) + (unsigned)(q * 16),
                  g_W1 + (size_t)(h0 + hh) * CDIM + q * 8);
        cpasync16(sptr(Wbs + hh * S1) + (unsigned)(q * 16),
                  g_W1 + (size_t)(HDIM + h0 + hh) * CDIM + q * 8);
    }
    const __nv_bfloat16* yb = g_Y + ((size_t)b * MDIM + mbase) * CDIM;
    g1_stageY(yb, Ybuf[0], tid);
    cpcommit();

    int wid = tid >> 5, lane = tid & 31;
    int gid = lane >> 2, tg = lane & 3;

    unsigned aY[2][2], waB, wbB;
    {
        int arow = (lane & 15), akoff = (lane >> 4) * 8;
#pragma unroll
        for (int buf = 0; buf < 2; buf++)
#pragma unroll
            for (int mt = 0; mt < 2; mt++)
                aY[buf][mt] = sptr(Ybuf[buf] + (mt * 16 + arow) * S1 + akoff);
        int brow = ((lane >> 4) << 3) + (lane & 7), bkoff = ((lane >> 3) & 1) * 8;
        waB = sptr(Was + (wid * 16 + brow) * S1 + bkoff);
        wbB = sptr(Wbs + (wid * 16 + brow) * S1 + bkoff);
    }

    int hg0 = h0 + wid * 16 + 0 * 8 + tg * 2;   // nt=0
    int hg1 = hg0 + 8;                           // nt=1
    float bi00 = b_in[hg0],        bi01 = b_in[hg0 + 1];
    float bg00 = b_in[HDIM + hg0], bg01 = b_in[HDIM + hg0 + 1];
    float bi10 = b_in[hg1],        bi11 = b_in[hg1 + 1];
    float bg10 = b_in[HDIM + hg1], bg11 = b_in[HDIM + hg1 + 1];

#pragma unroll
    for (int s = 0; s < G1SUB; s++) {
        if (s + 1 < G1SUB) {
            g1_stageY(yb + (size_t)(s + 1) * 32 * CDIM, Ybuf[(s + 1) & 1], tid);
            cpcommit();
            asm volatile("cp.async.wait_group 1;");
        } else {
            asm volatile("cp.async.wait_group 0;");
        }
        __syncthreads();

        float accA[2][2][4], accB[2][2][4];   // [mt][nt]
#pragma unroll
        for (int i = 0; i < 2; i++)
#pragma unroll
            for (int j = 0; j < 2; j++)
#pragma unroll
                for (int r = 0; r < 4; r++) { accA[i][j][r] = 0.f; accB[i][j][r] = 0.f; }

        const unsigned* asel = aY[s & 1];
#pragma unroll
        for (int kk = 0; kk < 128; kk += 16) {
            unsigned afr[2][4], waf[4], wbf[4];
            ldsm4(asel[0] + kk * 2, afr[0]);
            ldsm4(asel[1] + kk * 2, afr[1]);
            ldsm4(waB + kk * 2, waf);
            ldsm4(wbB + kk * 2, wbf);
#pragma unroll
            for (int nt = 0; nt < 2; nt++)
#pragma unroll
                for (int mt = 0; mt < 2; mt++) {
                    mma16816(accA[mt][nt], afr[mt], &waf[nt * 2]);
                    mma16816(accB[mt][nt], afr[mt], &wbf[nt * 2]);
                }
        }

        size_t m0s = mbase + (size_t)s * 32;
#pragma unroll
        for (int mt = 0; mt < 2; mt++) {
#pragma unroll
            for (int r = 0; r < 2; r++) {
                size_t m = m0s + mt * 16 + gid + r * 8;
                __nv_bfloat16* up = g_U + ((size_t)b * MDIM + m) * HDIM;
                float u0 = glu_f(accA[mt][0][r * 2 + 0] + bi00,
                                 accB[mt][0][r * 2 + 0] + bg00);
                float u1 = glu_f(accA[mt][0][r * 2 + 1] + bi01,
                                 accB[mt][0][r * 2 + 1] + bg01);
                *(__nv_bfloat162*)(up + hg0) = __floats2bfloat162_rn(u0, u1);
                u0 = glu_f(accA[mt][1][r * 2 + 0] + bi10,
                           accB[mt][1][r * 2 + 0] + bg10);
                u1 = glu_f(accA[mt][1][r * 2 + 1] + bi11,
                           accB[mt][1][r * 2 + 1] + bg11);
                *(__nv_bfloat162*)(up + hg1) = __floats2bfloat162_rn(u0, u1);
            }
        }
        __syncthreads();
    }
}

// ---------------- kernel 3: FUSED depthwise+SiLU+GEMM2+residual --------------
// 512 threads, 1 CTA/SM. W2 resident; U-halo double-buffered via cp.async with
// zero-fill; dw writes V subtile straight into Abuf; MMA (c=M, m=N) + residual
// epilogue per 32-t subtile. g_V eliminated (-268 MB DRAM traffic).
#define S2 264
#define FSUB 4                              /* 4 subtiles of 32 t = 128-t strip */
#define UHROWS (DWCH + 2)
#define DWCH 32
__global__ __launch_bounds__(512, 1) void k_dwg2(const float* __restrict__ w_dw,
                                                 const float* __restrict__ b_dw,
                                                 const float* __restrict__ x,
                                                 const float* __restrict__ b_out,
                                                 float* __restrict__ out) {
    extern __shared__ __nv_bfloat16 smf[];
    __nv_bfloat16* Ws   = smf;                         // [128 c][S2]
    __nv_bfloat16* Abuf = smf + 128 * S2;              // [32 m][S2]
    __nv_bfloat16* Uh[2];
    Uh[0] = smf + 160 * S2;                            // [3][34][HDIM]
    Uh[1] = Uh[0] + 3 * UHROWS * HDIM;
    int tid = threadIdx.x;
    int b = blockIdx.z, f = blockIdx.y, t0 = blockIdx.x * 128;

    const size_t HT = (size_t)TDIM * HDIM;
    const __nv_bfloat16* ub = g_U + (size_t)b * MDIM * HDIM;

    // stage halo for subtile s into Uh[s&1] (zero-fill edges)
    auto stageU = [&](int s) {
        int tc0 = t0 + s * DWCH;
        __nv_bfloat16* dst = Uh[s & 1];
#pragma unroll
        for (int i = tid; i < 3 * UHROWS * 32; i += 512) {
            int r = i / (UHROWS * 32);
            int rem = i - r * (UHROWS * 32);
            int tt = rem >> 5, q = rem & 31;
            int ff = f - 1 + r, t = tc0 - 2 + tt;
            bool ok = (ff >= 0 && ff < FDIM && t >= 0);
            const __nv_bfloat16* src = ok ? (ub + (size_t)ff * HT + (size_t)t * HDIM + q * 8)
                                          : ub;
            cpasync16z(sptr(dst + (r * UHROWS + tt) * HDIM) + (unsigned)(q * 16),
                       src, ok ? 16 : 0);
        }
    };

    // group 0: W2 + halo(0)
#pragma unroll
    for (int i = tid; i < 128 * 32; i += 512) {
        int c = i >> 5, q = i & 31;
        cpasync16(sptr(Ws + c * S2) + (unsigned)(q * 16),
                  g_W2 + (size_t)c * HDIM + q * 8);
    }
    stageU(0);
    cpcommit();

    // ---- per-thread dw params: 2 channels, 8 t-steps per subtile ----
    int hg = (tid & 127) * 2;
    int lt = (tid >> 7) * 8;             // 0,8,16,24
    __nv_bfloat162 wd2[9], bd2;
#pragma unroll
    for (int i = 0; i < 9; i++)
        wd2[i] = __floats2bfloat162_rn(w_dw[hg * 9 + i], w_dw[(hg + 1) * 9 + i]);
    bd2 = __floats2bfloat162_rn(b_dw[hg], b_dw[hg + 1]);

    // ---- MMA lane setup: 16 warps = 8 c-blocks x 2 m-blocks, warp 16c x 16m --
    int wid = tid >> 5, lane = tid & 31;
    int wc = wid & 7, wm8 = wid >> 3;
    int gid = lane >> 2, tg = lane & 3;
    unsigned aB, bB;
    {
        int arow = (lane & 15), akoff = (lane >> 4) * 8;
        aB = sptr(Ws + (wc * 16 + arow) * S2 + akoff);
        int brow = ((lane >> 4) << 3) + (lane & 7), bkoff = ((lane >> 3) & 1) * 8;
        bB = sptr(Abuf + (wm8 * 16 + brow) * S2 + bkoff);
    }
    int c0 = wc * 16 + gid;              // + r*8
    float bo0 = b_out[c0], bo1 = b_out[c0 + 8];

    size_t mstrip = (size_t)f * TDIM + t0;

#pragma unroll
    for (int s = 0; s < FSUB; s++) {
        if (s + 1 < FSUB) {
            stageU(s + 1);
            cpcommit();
            asm volatile("cp.async.wait_group 1;");
        } else {
            asm volatile("cp.async.wait_group 0;");
        }
        __syncthreads();   // halo(s) ready; also guards Abuf overwrite vs MMA(s-1)

        // ---- dw + SiLU: 2ch x 8t -> Abuf ----
        {
            const __nv_bfloat162* us2[3];
            const __nv_bfloat16* uhb = Uh[s & 1];
#pragma unroll
            for (int r = 0; r < 3; r++)
                us2[r] = (const __nv_bfloat162*)(uhb + (r * UHROWS + lt) * HDIM + hg);
            __nv_bfloat162 a0[3], a1[3];
#pragma unroll
            for (int r = 0; r < 3; r++) {
                a0[r] = us2[r][0];
                a1[r] = us2[r][HDIM / 2];
            }
#pragma unroll
            for (int j = 0; j < 8; j++) {
                __nv_bfloat162 cur[3];
#pragma unroll
                for (int r = 0; r < 3; r++)
                    cur[r] = us2[r][(2 + j) * (HDIM / 2)];
                __nv_bfloat162 acc = bd2;
                acc = __hfma2(a0[0], wd2[0], acc);
                acc = __hfma2(a1[0], wd2[1], acc);
                acc = __hfma2(cur[0], wd2[2], acc);
                acc = __hfma2(a0[1], wd2[3], acc);
                acc = __hfma2(a1[1], wd2[4], acc);
                acc = __hfma2(cur[1], wd2[5], acc);
                acc = __hfma2(a0[2], wd2[6], acc);
                acc = __hfma2(a1[2], wd2[7], acc);
                acc = __hfma2(cur[2], wd2[8], acc);
                float2 fv = __bfloat1622float2(acc);
                fv.x = silu_f(fv.x);
                fv.y = silu_f(fv.y);
                *(__nv_bfloat162*)(Abuf + (lt + j) * S2 + hg) =
                    __floats2bfloat162_rn(fv.x, fv.y);
#pragma unroll
                for (int r = 0; r < 3; r++) { a0[r] = a1[r]; a1[r] = cur[r]; }
            }
        }
        __syncthreads();   // Abuf complete before MMA reads

        // ---- MMA: 16c x 16m per warp, K=256 ----
        float acc[2][4];
#pragma unroll
        for (int j = 0; j < 2; j++)
#pragma unroll
            for (int r = 0; r < 4; r++) acc[j][r] = 0.f;
#pragma unroll
        for (int kk = 0; kk < 256; kk += 16) {
            unsigned afr[4], bfr[4];
            ldsm4(aB + kk * 2, afr);
            ldsm4(bB + kk * 2, bfr);
            mma16816(acc[0], afr, &bfr[0]);
            mma16816(acc[1], afr, &bfr[2]);
        }

        // ---- epilogue: out[b][c][m] = x + acc + b_out[c] ----
        size_t m0s = mstrip + (size_t)s * 32;
#pragma unroll
        for (int nt = 0; nt < 2; nt++) {
            int ml = wm8 * 16 + nt * 8 + tg * 2;
#pragma unroll
            for (int r = 0; r < 2; r++) {
                int c = c0 + r * 8;
                float bo = r ? bo1 : bo0;
                size_t idx = ((size_t)(b * CDIM + c)) * MDIM + m0s + ml;
                float2 xr = *(const float2*)(x + idx);
                float2 o;
                o.x = xr.x + acc[nt][r * 2 + 0] + bo;
                o.y = xr.y + acc[nt][r * 2 + 1] + bo;
                *(float2*)(out + idx) = o;
            }
        }
    }
}

// ---------------- launch ------------------------------------------------------
extern "C" void kernel_launch(void* const* d_in, const int* in_sizes, int n_in,
                              void* d_out, int out_size) {
    const float* x      = (const float*)d_in[0];
    const float* g_norm = (const float*)d_in[1];
    const float* w_in   = (const float*)d_in[2];
    const float* b_in   = (const float*)d_in[3];
    const float* w_dw   = (const float*)d_in[4];
    const float* b_dw   = (const float*)d_in[5];
    const float* w_out  = (const float*)d_in[6];
    const float* b_out  = (const float*)d_in[7];
    float* out = (float*)d_out;

    const int smem1 = 320 * S1 * (int)sizeof(__nv_bfloat16);              // 87040
    const int smemf = (160 * S2 + 2 * 3 * UHROWS * HDIM) * (int)sizeof(__nv_bfloat16); // 188928
    cudaFuncSetAttribute(k_gemm1, cudaFuncAttributeMaxDynamicSharedMemorySize, smem1);
    cudaFuncSetAttribute(k_dwg2,  cudaFuncAttributeMaxDynamicSharedMemorySize, smemf);

    k_prep<<<256, 256>>>(w_in, g_norm, w_out);
    k_rms<<<dim3(TDIM / 64, FDIM, BATCH), 256>>>(x, g_norm);
    k_gemm1<<<dim3(MDIM / 256, HDIM / 128, BATCH), 256, smem1>>>(b_in);
    k_dwg2<<<dim3(TDIM / 128, FDIM, BATCH), 512, smemf>>>(w_dw, b_dw, x, b_out, out);
}

// round 16
// speedup vs baseline: 1.1036x; 1.1036x over previous
#include <cuda_runtime.h>
#include <cuda_bf16.h>

#define BATCH 4
#define CDIM 128
#define FDIM 128
#define TDIM 512
#define HDIM 256
#define MDIM (FDIM*TDIM)   /* 65536 positions per batch */
#define EPSV 1e-6f

__device__ __forceinline__ float silu_f(float v) {
    return __fdividef(v, 1.f + __expf(-v));
}
__device__ __forceinline__ float glu_f(float a, float g) {
    return __fdividef(a, 1.f + __expf(-g));
}

// ---------------- scratch (static device globals; no runtime alloc) ----------
__device__ __nv_bfloat16 g_Y[(size_t)BATCH * MDIM * CDIM];   //  64 MB  [b][m][c]
__device__ __nv_bfloat16 g_U[(size_t)BATCH * MDIM * HDIM];   // 128 MB  [b][m][h]
__device__ __nv_bfloat16 g_V[(size_t)BATCH * MDIM * HDIM];   // 128 MB  [b][m][h]
__device__ __nv_bfloat16 g_W1[2 * HDIM * CDIM];              // w_in * g_norm (bf16)
__device__ __nv_bfloat16 g_W2[CDIM * HDIM];                  // w_out (bf16)

// ---------------- kernel 0: weight prep --------------------------------------
__global__ void k_prep(const float* __restrict__ w_in,
                       const float* __restrict__ gn,
                       const float* __restrict__ w_out) {
    int i = blockIdx.x * 256 + threadIdx.x;
    if (i < 2 * HDIM * CDIM)
        g_W1[i] = __float2bfloat16(w_in[i] * gn[i & (CDIM - 1)]);
    if (i < CDIM * HDIM)
        g_W2[i] = __float2bfloat16(w_out[i]);
}

// ---------------- kernel 1: RMSNorm + transpose to [m][c] bf16 ---------------
__global__ __launch_bounds__(256) void k_rms(const float* __restrict__ x,
                                             const float* __restrict__ gn) {
    __shared__ float xs[CDIM][65];   // [c][t] padded
    __shared__ float ps[4][64];
    __shared__ float ssc[64];
    __shared__ float gs[CDIM];
    int b = blockIdx.z, f = blockIdx.y, t0 = blockIdx.x * 64;
    int tid = threadIdx.x;
    const float* xb = x + ((size_t)(b * CDIM) * FDIM + f) * TDIM + t0;
    for (int i = tid; i < CDIM * 16; i += 256) {
        int c = i >> 4, q = i & 15;
        float4 v = *(const float4*)(xb + (size_t)c * FDIM * TDIM + q * 4);
        xs[c][q * 4 + 0] = v.x;
        xs[c][q * 4 + 1] = v.y;
        xs[c][q * 4 + 2] = v.z;
        xs[c][q * 4 + 3] = v.w;
    }
    if (tid < CDIM) gs[tid] = gn[tid];
    __syncthreads();
    {
        int t = tid & 63, cs = (tid >> 6) * 32;
        float s = 0.f;
#pragma unroll
        for (int c = 0; c < 32; c++) { float v = xs[cs + c][t]; s += v * v; }
        ps[tid >> 6][t] = s;
    }
    __syncthreads();
    if (tid < 64) {
        float s = ps[0][tid] + ps[1][tid] + ps[2][tid] + ps[3][tid];
        ssc[tid] = rsqrtf(s * (1.0f / CDIM) + EPSV);
    }
    __syncthreads();
    __nv_bfloat16* yb = g_Y + ((size_t)b * MDIM + (size_t)f * TDIM + t0) * CDIM;
    for (int i = tid; i < 64 * 64; i += 256) {
        int t = i >> 6, cp = i & 63;
        float sc = ssc[t];
        float v0 = xs[2 * cp][t] * sc * gs[2 * cp];
        float v1 = xs[2 * cp + 1][t] * sc * gs[2 * cp + 1];
        *(__nv_bfloat162*)(yb + (size_t)t * CDIM + 2 * cp) =
            __floats2bfloat162_rn(v0, v1);
    }
}

// ---------------- mma / ldmatrix / cp.async helpers ---------------------------
__device__ __forceinline__ void mma16816(float* d, const unsigned* a, const unsigned* bb) {
    asm volatile(
        "mma.sync.aligned.m16n8k16.row.col.f32.bf16.bf16.f32 "
        "{%0,%1,%2,%3},{%4,%5,%6,%7},{%8,%9},{%0,%1,%2,%3};\n"
        : "+f"(d[0]), "+f"(d[1]), "+f"(d[2]), "+f"(d[3])
        : "r"(a[0]), "r"(a[1]), "r"(a[2]), "r"(a[3]), "r"(bb[0]), "r"(bb[1]));
}
__device__ __forceinline__ unsigned sptr(const void* p) {
    unsigned r;
    asm("{.reg .u64 t; cvta.to.shared.u64 t, %1; cvt.u32.u64 %0, t;}" : "=r"(r) : "l"(p));
    return r;
}
__device__ __forceinline__ void ldsm4(unsigned addr, unsigned* r) {
    asm volatile("ldmatrix.sync.aligned.m8n8.x4.shared.b16 {%0,%1,%2,%3},[%4];"
                 : "=r"(r[0]), "=r"(r[1]), "=r"(r[2]), "=r"(r[3]) : "r"(addr));
}
__device__ __forceinline__ void cpasync16(unsigned dst, const void* src) {
    asm volatile("cp.async.cg.shared.global [%0], [%1], 16;" :: "r"(dst), "l"(src));
}
__device__ __forceinline__ void cpasync16z(unsigned dst, const void* src, int srcsz) {
    asm volatile("cp.async.cg.shared.global [%0], [%1], 16, %2;"
                 :: "r"(dst), "l"(src), "r"(srcsz));
}
__device__ __forceinline__ void cpcommit() {
    asm volatile("cp.async.commit_group;");
}

// ---------------- kernel 2: GEMM1 pipelined (cp.async, W1-half resident) -----
// 16 m-subtiles of 32 (512 m per CTA): weights staged once per 512 m.
#define S1 136   // smem row stride (elems)
#define G1SUB 16
__device__ __forceinline__ void g1_stageY(const __nv_bfloat16* src,
                                          __nv_bfloat16* dst, int tid) {
#pragma unroll
    for (int i = tid; i < 32 * 16; i += 256) {
        int m = i >> 4, q = i & 15;
        cpasync16(sptr(dst + m * S1) + (unsigned)(q * 16),
                  src + (size_t)m * CDIM + q * 8);
    }
}
__global__ __launch_bounds__(256, 2) void k_gemm1(const float* __restrict__ b_in) {
    extern __shared__ __nv_bfloat16 sm1[];
    __nv_bfloat16* Was = sm1;                  // [128][S1]
    __nv_bfloat16* Wbs = sm1 + 128 * S1;       // [128][S1]
    __nv_bfloat16* Ybuf[2];
    Ybuf[0] = sm1 + 256 * S1;                  // [32][S1]
    Ybuf[1] = Ybuf[0] + 32 * S1;               // [32][S1]
    int b = blockIdx.z;
    int h0 = blockIdx.y * 128;
    size_t mbase = (size_t)blockIdx.x * (32 * G1SUB);
    int tid = threadIdx.x;

#pragma unroll
    for (int i = tid; i < 128 * 16; i += 256) {
        int hh = i >> 4, q = i & 15;
        cpasync16(sptr(Was + hh * S1) + (unsigned)(q * 16),
                  g_W1 + (size_t)(h0 + hh) * CDIM + q * 8);
        cpasync16(sptr(Wbs + hh * S1) + (unsigned)(q * 16),
                  g_W1 + (size_t)(HDIM + h0 + hh) * CDIM + q * 8);
    }
    const __nv_bfloat16* yb = g_Y + ((size_t)b * MDIM + mbase) * CDIM;
    g1_stageY(yb, Ybuf[0], tid);
    cpcommit();

    int wid = tid >> 5, lane = tid & 31;
    int gid = lane >> 2, tg = lane & 3;

    unsigned aY[2][2], waB, wbB;
    {
        int arow = (lane & 15), akoff = (lane >> 4) * 8;
#pragma unroll
        for (int buf = 0; buf < 2; buf++)
#pragma unroll
            for (int mt = 0; mt < 2; mt++)
                aY[buf][mt] = sptr(Ybuf[buf] + (mt * 16 + arow) * S1 + akoff);
        int brow = ((lane >> 4) << 3) + (lane & 7), bkoff = ((lane >> 3) & 1) * 8;
        waB = sptr(Was + (wid * 16 + brow) * S1 + bkoff);
        wbB = sptr(Wbs + (wid * 16 + brow) * S1 + bkoff);
    }

    int hg0 = h0 + wid * 16 + 0 * 8 + tg * 2;   // nt=0
    int hg1 = hg0 + 8;                           // nt=1
    float bi00 = b_in[hg0],        bi01 = b_in[hg0 + 1];
    float bg00 = b_in[HDIM + hg0], bg01 = b_in[HDIM + hg0 + 1];
    float bi10 = b_in[hg1],        bi11 = b_in[hg1 + 1];
    float bg10 = b_in[HDIM + hg1], bg11 = b_in[HDIM + hg1 + 1];

#pragma unroll 2
    for (int s = 0; s < G1SUB; s++) {
        if (s + 1 < G1SUB) {
            g1_stageY(yb + (size_t)(s + 1) * 32 * CDIM, Ybuf[(s + 1) & 1], tid);
            cpcommit();
            asm volatile("cp.async.wait_group 1;");
        } else {
            asm volatile("cp.async.wait_group 0;");
        }
        __syncthreads();

        float accA[2][2][4], accB[2][2][4];   // [mt][nt]
#pragma unroll
        for (int i = 0; i < 2; i++)
#pragma unroll
            for (int j = 0; j < 2; j++)
#pragma unroll
                for (int r = 0; r < 4; r++) { accA[i][j][r] = 0.f; accB[i][j][r] = 0.f; }

        const unsigned* asel = aY[s & 1];
#pragma unroll
        for (int kk = 0; kk < 128; kk += 16) {
            unsigned afr[2][4], waf[4], wbf[4];
            ldsm4(asel[0] + kk * 2, afr[0]);
            ldsm4(asel[1] + kk * 2, afr[1]);
            ldsm4(waB + kk * 2, waf);
            ldsm4(wbB + kk * 2, wbf);
#pragma unroll
            for (int nt = 0; nt < 2; nt++)
#pragma unroll
                for (int mt = 0; mt < 2; mt++) {
                    mma16816(accA[mt][nt], afr[mt], &waf[nt * 2]);
                    mma16816(accB[mt][nt], afr[mt], &wbf[nt * 2]);
                }
        }

        size_t m0s = mbase + (size_t)s * 32;
#pragma unroll
        for (int mt = 0; mt < 2; mt++) {
#pragma unroll
            for (int r = 0; r < 2; r++) {
                size_t m = m0s + mt * 16 + gid + r * 8;
                __nv_bfloat16* up = g_U + ((size_t)b * MDIM + m) * HDIM;
                float u0 = glu_f(accA[mt][0][r * 2 + 0] + bi00,
                                 accB[mt][0][r * 2 + 0] + bg00);
                float u1 = glu_f(accA[mt][0][r * 2 + 1] + bi01,
                                 accB[mt][0][r * 2 + 1] + bg01);
                *(__nv_bfloat162*)(up + hg0) = __floats2bfloat162_rn(u0, u1);
                u0 = glu_f(accA[mt][1][r * 2 + 0] + bi10,
                           accB[mt][1][r * 2 + 0] + bg10);
                u1 = glu_f(accA[mt][1][r * 2 + 1] + bi11,
                           accB[mt][1][r * 2 + 1] + bg11);
                *(__nv_bfloat162*)(up + hg1) = __floats2bfloat162_rn(u0, u1);
            }
        }
        __syncthreads();
    }
}

// ---------------- kernel 3: depthwise 3x3 + SiLU (2ch/thread, HFMA2) ---------
// cp.async staging with hardware zero-fill halo (bypasses L1tex + regfile).
#define DWC 32
#define DWSM (3 * (DWC + 2) * HDIM)    /* 26112 elems = 52224 B */
__global__ __launch_bounds__(256, 4) void k_dw(const float* __restrict__ w_dw,
                                               const float* __restrict__ b_dw) {
    extern __shared__ __nv_bfloat16 Us[];   // [3][34][HDIM]
    int tid = threadIdx.x;
    int b = blockIdx.z, f = blockIdx.y, t0 = blockIdx.x * DWC;

    const size_t HT = (size_t)TDIM * HDIM;
    const __nv_bfloat16* ub = g_U + (size_t)b * MDIM * HDIM;
#pragma unroll
    for (int i = tid; i < 3 * (DWC + 2) * 32; i += 256) {
        int r = i / ((DWC + 2) * 32);
        int rem = i - r * ((DWC + 2) * 32);
        int tt = rem >> 5, q = rem & 31;
        int ff = f - 1 + r, t = t0 - 2 + tt;
        bool ok = (ff >= 0 && ff < FDIM && t >= 0);
        const __nv_bfloat16* src = ok ? (ub + (size_t)ff * HT + (size_t)t * HDIM + q * 8)
                                      : ub;
        cpasync16z(sptr(Us + (r * (DWC + 2) + tt) * HDIM) + (unsigned)(q * 16),
                   src, ok ? 16 : 0);
    }
    cpcommit();
    asm volatile("cp.async.wait_group 0;");
    __syncthreads();

    int hg = (tid & 127) * 2;
    int lt = (tid >> 7) * 16;        // 0 or 16

    __nv_bfloat162 wd2[9], bd2;
#pragma unroll
    for (int i = 0; i < 9; i++)
        wd2[i] = __floats2bfloat162_rn(w_dw[hg * 9 + i], w_dw[(hg + 1) * 9 + i]);
    bd2 = __floats2bfloat162_rn(b_dw[hg], b_dw[hg + 1]);

    const __nv_bfloat162* us2[3];
#pragma unroll
    for (int r = 0; r < 3; r++)
        us2[r] = (const __nv_bfloat162*)(Us + (r * (DWC + 2) + lt) * HDIM + hg);

    __nv_bfloat162 a0[3], a1[3];
#pragma unroll
    for (int r = 0; r < 3; r++) {
        a0[r] = us2[r][0];
        a1[r] = us2[r][HDIM / 2];
    }

    __nv_bfloat16* vout = g_V + ((size_t)b * MDIM + (size_t)f * TDIM + t0 + lt) * HDIM + hg;
#pragma unroll
    for (int j = 0; j < 16; j++) {
        __nv_bfloat162 cur[3];
#pragma unroll
        for (int r = 0; r < 3; r++)
            cur[r] = us2[r][(2 + j) * (HDIM / 2)];
        __nv_bfloat162 acc = bd2;
        acc = __hfma2(a0[0], wd2[0], acc);
        acc = __hfma2(a1[0], wd2[1], acc);
        acc = __hfma2(cur[0], wd2[2], acc);
        acc = __hfma2(a0[1], wd2[3], acc);
        acc = __hfma2(a1[1], wd2[4], acc);
        acc = __hfma2(cur[1], wd2[5], acc);
        acc = __hfma2(a0[2], wd2[6], acc);
        acc = __hfma2(a1[2], wd2[7], acc);
        acc = __hfma2(cur[2], wd2[8], acc);
        float2 fv = __bfloat1622float2(acc);
        fv.x = silu_f(fv.x);
        fv.y = silu_f(fv.y);
        *(__nv_bfloat162*)vout = __floats2bfloat162_rn(fv.x, fv.y);
        vout += HDIM;
#pragma unroll
        for (int r = 0; r < 3; r++) { a0[r] = a1[r]; a1[r] = cur[r]; }
    }
}

// ---------------- kernel 4: GEMM2 pipelined (cp.async, W2 resident) ----------
#define S2 264
#define G2SUB 8
__device__ __forceinline__ void g2_stageV(const __nv_bfloat16* src,
                                          __nv_bfloat16* dst, int tid) {
#pragma unroll
    for (int i = tid; i < 32 * 32; i += 256) {
        int m = i >> 5, q = i & 31;
        cpasync16(sptr(dst + m * S2) + (unsigned)(q * 16),
                  src + (size_t)m * HDIM + q * 8);
    }
}
__global__ __launch_bounds__(256, 2) void k_gemm2(const float* __restrict__ x,
                                                  const float* __restrict__ b_out,
                                                  float* __restrict__ out) {
    extern __shared__ __nv_bfloat16 sm2[];
    __nv_bfloat16* Ws  = sm2;                  // [128 c][S2]  w_out
    __nv_bfloat16* Abuf[2];
    Abuf[0] = sm2 + 128 * S2;                  // [32 m][S2]
    Abuf[1] = Abuf[0] + 32 * S2;               // [32 m][S2]
    int b = blockIdx.z;
    size_t mbase = (size_t)blockIdx.x * 256;
    int tid = threadIdx.x;

#pragma unroll
    for (int i = tid; i < 128 * 32; i += 256) {
        int c = i >> 5, q = i & 31;
        cpasync16(sptr(Ws + c * S2) + (unsigned)(q * 16),
                  g_W2 + (size_t)c * HDIM + q * 8);
    }
    const __nv_bfloat16* vb = g_V + ((size_t)b * MDIM + mbase) * HDIM;
    g2_stageV(vb, Abuf[0], tid);
    cpcommit();

    int wid = tid >> 5, lane = tid & 31;
    int gid = lane >> 2, tg = lane & 3;

    unsigned aB, bB[2][2];
    {
        int arow = (lane & 15), akoff = (lane >> 4) * 8;
        aB = sptr(Ws + (wid * 16 + arow) * S2 + akoff);
        int brow = ((lane >> 4) << 3) + (lane & 7), bkoff = ((lane >> 3) & 1) * 8;
#pragma unroll
        for (int buf = 0; buf < 2; buf++)
#pragma unroll
            for (int p = 0; p < 2; p++)
                bB[buf][p] = sptr(Abuf[buf] + (p * 16 + brow) * S2 + bkoff);
    }

#pragma unroll
    for (int s = 0; s < G2SUB; s++) {
        if (s + 1 < G2SUB) {
            g2_stageV(vb + (size_t)(s + 1) * 32 * HDIM, Abuf[(s + 1) & 1], tid);
            cpcommit();
            asm volatile("cp.async.wait_group 1;");
        } else {
            asm volatile("cp.async.wait_group 0;");
        }
        __syncthreads();

        float acc[4][4];
#pragma unroll
        for (int j = 0; j < 4; j++)
#pragma unroll
            for (int r = 0; r < 4; r++) acc[j][r] = 0.f;

        const unsigned* bsel = bB[s & 1];
#pragma unroll
        for (int kk = 0; kk < 256; kk += 16) {
            unsigned afr[4], bfr[2][4];
            ldsm4(aB + kk * 2, afr);
            ldsm4(bsel[0] + kk * 2, bfr[0]);
            ldsm4(bsel[1] + kk * 2, bfr[1]);
#pragma unroll
            for (int nt = 0; nt < 4; nt++)
                mma16816(acc[nt], afr, &bfr[nt >> 1][(nt & 1) * 2]);
        }

        size_t m0s = mbase + (size_t)s * 32;
#pragma unroll
        for (int nt = 0; nt < 4; nt++) {
            int ml = nt * 8 + tg * 2;
#pragma unroll
            for (int r = 0; r < 2; r++) {
                int c = wid * 16 + gid + r * 8;
                float bo = b_out[c];
                size_t idx = ((size_t)(b * CDIM + c)) * MDIM + m0s + ml;
                float2 xr = *(const float2*)(x + idx);
                float2 o;
                o.x = xr.x + acc[nt][r * 2 + 0] + bo;
                o.y = xr.y + acc[nt][r * 2 + 1] + bo;
                *(float2*)(out + idx) = o;
            }
        }
        __syncthreads();
    }
}

// ---------------- launch ------------------------------------------------------
extern "C" void kernel_launch(void* const* d_in, const int* in_sizes, int n_in,
                              void* d_out, int out_size) {
    const float* x      = (const float*)d_in[0];
    const float* g_norm = (const float*)d_in[1];
    const float* w_in   = (const float*)d_in[2];
    const float* b_in   = (const float*)d_in[3];
    const float* w_dw   = (const float*)d_in[4];
    const float* b_dw   = (const float*)d_in[5];
    const float* w_out  = (const float*)d_in[6];
    const float* b_out  = (const float*)d_in[7];
    float* out = (float*)d_out;

    const int smem1 = 320 * S1 * (int)sizeof(__nv_bfloat16);   // 87040
    const int smemd = DWSM * (int)sizeof(__nv_bfloat16);       // 52224
    const int smem2 = 192 * S2 * (int)sizeof(__nv_bfloat16);   // 101376
    cudaFuncSetAttribute(k_gemm1, cudaFuncAttributeMaxDynamicSharedMemorySize, smem1);
    cudaFuncSetAttribute(k_dw,    cudaFuncAttributeMaxDynamicSharedMemorySize, smemd);
    cudaFuncSetAttribute(k_gemm2, cudaFuncAttributeMaxDynamicSharedMemorySize, smem2);

    k_prep<<<256, 256>>>(w_in, g_norm, w_out);
    k_rms<<<dim3(TDIM / 64, FDIM, BATCH), 256>>>(x, g_norm);
    k_gemm1<<<dim3(MDIM / (32 * G1SUB), HDIM / 128, BATCH), 256, smem1>>>(b_in);
    k_dw<<<dim3(TDIM / DWC, FDIM, BATCH), 256, smemd>>>(w_dw, b_dw);
    k_gemm2<<<dim3(MDIM / 256, 1, BATCH), 256, smem2>>>(x, b_out, out);
}